// round 9
// baseline (speedup 1.0000x reference)
#include <cuda_runtime.h>

#define BB   32
#define NN   1024
#define WW_  128
#define RR   4
#define SEQ  512
#define DIN  512
#define IFACE 919

// Flattened output offsets (tuple concat order: out, memory, link, usage, prec, ww, rw)
#define OUT_OFF    0ull
#define MEM_OFF    16384ull
#define LINK_OFF   4210688ull
#define USAGE_OFF  37765120ull
#define PREC_OFF   37797888ull
#define WWO_OFF    37830656ull
#define RW_OFF     37863424ull
#define LINK_F4    8388608ull      // 33,554,432 floats / 4

#define MEAN_BLKS  512
#define ZERO_BLKS  2048            // 2048*256*16 == LINK_F4 exactly
#define N1_BLKS    (MEAN_BLKS + ZERO_BLKS)

#define FILL_BLKS  4096            // 128 blocks per batch
#define N2_BLKS    (BB + FILL_BLKS)

// Scratch (no allocations allowed)
__device__ float g_part[32 * BB * DIN];
__device__ float g_er[BB * WW_];
__device__ float g_wv[BB * WW_];
__device__ int   g_flag[BB];

__device__ __forceinline__ float sigmoidf(float x) {
    return 1.0f / (1.0f + expf(-x));
}

// ---------------------------------------------------------------------------
// Node 1: fused link-zero (134MB, __stcs evict-first, exactly 16 stores/thread)
//         + mean partials of x (33.5MB, __ldcs streaming reads)
//         + per-replay flag reset (block 0, strictly ordered before node 2).
// grid 2560 x 256. (unchanged from the 63.5us version except flag reset)
// ---------------------------------------------------------------------------
__global__ void __launch_bounds__(256)
k1_zero_mean(const float* __restrict__ x, float* __restrict__ out) {
    int bid = blockIdx.x, t = threadIdx.x;
    if (bid < MEAN_BLKS) {
        if (bid == 0 && t < BB) g_flag[t] = 0;   // reset flags for node 2
        // block (b, c): 32-row chunk c of batch b; threads split into 2 halves
        int b = bid >> 4, c = bid & 15;
        int col = t & 127;          // float4 column (512 floats / 4)
        int h   = t >> 7;           // 16-row half
        int cc  = c * 2 + h;        // chunk-half id in [0, 32)
        const float4* xp = (const float4*)(x + (size_t)b * SEQ * DIN);
        float4 acc = make_float4(0.f, 0.f, 0.f, 0.f);
        int s0 = c * 32 + h * 16;
#pragma unroll
        for (int s = s0; s < s0 + 16; s += 2) {   // 2-way ILP on the loads
            float4 v0 = __ldcs(&xp[s * 128 + col]);
            float4 v1 = __ldcs(&xp[(s + 1) * 128 + col]);
            acc.x += v0.x + v1.x; acc.y += v0.y + v1.y;
            acc.z += v0.z + v1.z; acc.w += v0.w + v1.w;
        }
        ((float4*)g_part)[(cc * BB + b) * 128 + col] = acc;
    } else {
        float4 z = make_float4(0.f, 0.f, 0.f, 0.f);
        float4* p = (float4*)(out + LINK_OFF);
        size_t base = (size_t)(bid - MEAN_BLKS) * 256 + t;
        size_t stride = (size_t)ZERO_BLKS * 256;
#pragma unroll
        for (int i = 0; i < 16; i++)            // exact cover, no bounds check
            __stcs(&p[base + (size_t)i * stride], z);
    }
}

// ---------------------------------------------------------------------------
// Node 2 (fused k2+k3): 32 compute blocks + 4096 fill blocks.
//  bid 0..31  : batch compute -> small sections -> fence -> flag[b]=1
//  bid 32+    : fill 256 float4 of memory for batch b after flag[b] observed.
// Compute blocks have the lowest bids -> scheduled first -> no deadlock.
// ---------------------------------------------------------------------------
__global__ void __launch_bounds__(256)
k23_fused(const float* __restrict__ Wm, float* __restrict__ out) {
    int bid = blockIdx.x, t = threadIdx.x;

    if (bid < BB) {
        // ----------------- compute role: one block per batch -----------------
        int b = bid;
        __shared__ float mx[DIN];
        __shared__ float s_rm1[RR], s_fg[RR], s_q[RR];
        __shared__ float s_pw[16];
        __shared__ float s_c1, s_c2, s_u;

        for (int i = t; i < DIN; i += 256) {
            float s = 0.f;
#pragma unroll
            for (int c = 0; c < 32; c++) s += g_part[(c * BB + b) * DIN + i];
            mx[i] = s * (1.0f / 512.0f);
        }
        __syncthreads();

        // iface[j] = mean . W[:,j] for j in [645, 919) only
        float f_loc[2];
        int   j_loc[2];
        int nj = 0;
        for (int j = 645 + t; j < IFACE; j += 256) {
            float acc = 0.f;
#pragma unroll 8
            for (int k = 0; k < DIN; k++) acc = fmaf(mx[k], Wm[k * IFACE + j], acc);
            f_loc[nj] = acc; j_loc[nj] = j; nj++;
        }
        __syncthreads();
        // scatter: mx[0..127]=erase raw, [128..255]=write_vec, [256..259]=free
        // gates, [260]=alloc gate, [261]=write gate, [262..273]=read modes
        for (int i = 0; i < nj; i++) mx[j_loc[i] - 645] = f_loc[i];
        __syncthreads();

        if (t < 128) {
            g_er[b * WW_ + t] = sigmoidf(mx[t]);
            g_wv[b * WW_ + t] = mx[128 + t];
        }
        if (t < RR) {
            float m0 = mx[262 + t], m1 = mx[266 + t], m2 = mx[270 + t];
            float mmax = fmaxf(m0, fmaxf(m1, m2));
            float e0 = expf(m0 - mmax), e1 = expf(m1 - mmax), e2 = expf(m2 - mmax);
            float rm1 = e1 / (e0 + e1 + e2);
            s_rm1[t] = rm1;
            float q = rm1 * (1.0f / 1024.0f);   // exact /2^10
            s_q[t] = q;
            s_fg[t] = sigmoidf(mx[256 + t]);
        }
        __syncthreads();
        if (t == 0) {
            float ret = 1.0f;
#pragma unroll
            for (int r = 0; r < RR; r++) ret *= (1.0f - s_fg[r] * s_q[r]);
            float u = 1e-6f * ret;              // usage (constant over n)
            s_u = u;
            float ag = sigmoidf(mx[260]);
            float wg = sigmoidf(mx[261]);
            s_c1 = wg * ag * (1.0f - u);
            s_c2 = wg * (1.0f - ag) * (1.0f / 1024.0f);
            float sh = 1.0f;                    // exact sequential cumprod prefix
#pragma unroll
            for (int i = 0; i < 16; i++) { s_pw[i] = sh; sh *= u; }
        }
        __syncthreads();

        // out[b, w*4+r] = 1e-6 * rm1[r]   (write-only -> evict-first)
        if (t < 128) {
            float4 ov = make_float4(1e-6f * s_rm1[0], 1e-6f * s_rm1[1],
                                    1e-6f * s_rm1[2], 1e-6f * s_rm1[3]);
            __stcs(&((float4*)(out + OUT_OFF))[b * 128 + t], ov);
        }
        // ww (re-read by fill blocks -> cached) / prec / usage / rw (write-only)
        float c1 = s_c1, c2 = s_c2, u = s_u;
        float4 q4 = make_float4(s_q[0], s_q[1], s_q[2], s_q[3]);
#pragma unroll
        for (int n = t; n < NN; n += 256) {
            float shifted = (n < 16) ? s_pw[n] : 0.0f;
            float ww = fmaf(c1, shifted, c2);
            out[WWO_OFF + (size_t)b * NN + n] = ww;           // cached
            __stcs(out + PREC_OFF + (size_t)b * NN + n, ww);
            __stcs(out + USAGE_OFF + (size_t)b * NN + n, u);
            __stcs(&((float4*)(out + RW_OFF))[b * NN + n], q4);
        }
        __syncthreads();
        if (t == 0) { __threadfence(); atomicExch(&g_flag[b], 1); }
    } else {
        // ----------------- fill role: 128 blocks per batch --------------------
        int r = bid - BB;
        int b = r >> 7;                 // batch
        int q = r & 127;                // block within batch
        if (t == 0) {
            while (atomicAdd(&g_flag[b], 0) == 0) __nanosleep(64);
            __threadfence();
        }
        __syncthreads();

        int v = b * 32768 + q * 256 + t;   // float4 index into memory
        int rem = v & 32767;
        int n  = rem >> 5;
        int w4 = rem & 31;
        float ww = __ldg(out + WWO_OFF + (size_t)b * NN + n);
        float4 e  = ((const float4*)g_er)[b * 32 + w4];
        float4 wv = ((const float4*)g_wv)[b * 32 + w4];
        float4 m;
        m.x = 1e-6f * (1.0f - ww * e.x) + ww * wv.x;
        m.y = 1e-6f * (1.0f - ww * e.y) + ww * wv.y;
        m.z = 1e-6f * (1.0f - ww * e.z) + ww * wv.z;
        m.w = 1e-6f * (1.0f - ww * e.w) + ww * wv.w;
        __stcs(&((float4*)(out + MEM_OFF))[v], m);
    }
}

extern "C" void kernel_launch(void* const* d_in, const int* in_sizes, int n_in,
                              void* d_out, int out_size) {
    const float* x  = (const float*)d_in[0];
    const float* Wm = (const float*)d_in[1];
    float* out = (float*)d_out;

    k1_zero_mean<<<N1_BLKS, 256>>>(x, out);
    k23_fused<<<N2_BLKS, 256>>>(Wm, out);
}

// round 10
// speedup vs baseline: 1.0601x; 1.0601x over previous
#include <cuda_runtime.h>

#define BB   32
#define NN   1024
#define WW_  128
#define RR   4
#define SEQ  512
#define DIN  512
#define IFACE 919

// Flattened output offsets (tuple concat order: out, memory, link, usage, prec, ww, rw)
#define OUT_OFF    0ull
#define MEM_OFF    16384ull
#define LINK_OFF   4210688ull
#define USAGE_OFF  37765120ull
#define PREC_OFF   37797888ull
#define WWO_OFF    37830656ull
#define RW_OFF     37863424ull
#define LINK_F4    8388608ull      // 33,554,432 floats / 4

#define MEM_BLKS   1024            // memory fill: 4 f4/thread
#define ZERO_BLKS  2048            // link zero: 16 f4/thread (exact cover)
#define N3_BLKS    (MEM_BLKS + ZERO_BLKS)

// Scratch (no allocations allowed)
__device__ float g_part[64 * BB * DIN];   // 64 chunk-halves per batch (4MB)
__device__ float g_er[BB * WW_];
__device__ float g_wv[BB * WW_];

__device__ __forceinline__ float sigmoidf(float x) {
    return 1.0f / (1.0f + expf(-x));
}

// ---------------------------------------------------------------------------
// Node 1: PURE READ. mean partials of x (33.5MB, __ldcs streaming).
// grid 1024 x 256: block (b, c), c in [0,32) covers 16 seq rows;
// threads split into 2 halves of 8 rows. 64 partial chunks per batch.
// ---------------------------------------------------------------------------
__global__ void __launch_bounds__(256)
k1_mean(const float* __restrict__ x) {
    int bid = blockIdx.x, t = threadIdx.x;
    int b = bid >> 5, c = bid & 31;
    int col = t & 127;          // float4 column (512 floats / 4)
    int h   = t >> 7;           // 8-row half
    int cc  = c * 2 + h;        // chunk-half id in [0, 64)
    const float4* xp = (const float4*)(x + (size_t)b * SEQ * DIN);
    float4 acc = make_float4(0.f, 0.f, 0.f, 0.f);
    int s0 = c * 16 + h * 8;
#pragma unroll
    for (int s = s0; s < s0 + 8; s += 2) {      // 2-way ILP on the loads
        float4 v0 = __ldcs(&xp[s * 128 + col]);
        float4 v1 = __ldcs(&xp[(s + 1) * 128 + col]);
        acc.x += v0.x + v1.x; acc.y += v0.y + v1.y;
        acc.z += v0.z + v1.z; acc.w += v0.w + v1.w;
    }
    ((float4*)g_part)[(cc * BB + b) * 128 + col] = acc;
}

// ---------------------------------------------------------------------------
// Node 2: one block per batch. Combine 64 partial chunks -> mean (smem),
// compute ONLY the needed iface columns [645,919), activations, then write
// all small output sections: out, ww, prec, usage, rw (~1.3MB total).
// ---------------------------------------------------------------------------
__global__ void __launch_bounds__(256)
k2_batch(const float* __restrict__ Wm, float* __restrict__ out) {
    int b = blockIdx.x, t = threadIdx.x;
    __shared__ float mx[DIN];
    __shared__ float s_rm1[RR], s_fg[RR], s_q[RR];
    __shared__ float s_pw[16];
    __shared__ float s_c1, s_c2, s_u;

    for (int i = t; i < DIN; i += 256) {
        float s = 0.f;
#pragma unroll
        for (int c = 0; c < 64; c++) s += g_part[(c * BB + b) * DIN + i];
        mx[i] = s * (1.0f / 512.0f);
    }
    __syncthreads();

    // iface[j] = mean . W[:,j] for j in [645, 919) only
    float f_loc[2];
    int   j_loc[2];
    int nj = 0;
    for (int j = 645 + t; j < IFACE; j += 256) {
        float acc = 0.f;
#pragma unroll 8
        for (int k = 0; k < DIN; k++) acc = fmaf(mx[k], Wm[k * IFACE + j], acc);
        f_loc[nj] = acc; j_loc[nj] = j; nj++;
    }
    __syncthreads();
    // scatter: mx[0..127]=erase raw, [128..255]=write_vec, [256..259]=free gates,
    // [260]=alloc gate, [261]=write gate, [262..273]=read modes
    for (int i = 0; i < nj; i++) mx[j_loc[i] - 645] = f_loc[i];
    __syncthreads();

    if (t < 128) {
        g_er[b * WW_ + t] = sigmoidf(mx[t]);
        g_wv[b * WW_ + t] = mx[128 + t];
    }
    if (t < RR) {
        float m0 = mx[262 + t], m1 = mx[266 + t], m2 = mx[270 + t];
        float mmax = fmaxf(m0, fmaxf(m1, m2));
        float e0 = expf(m0 - mmax), e1 = expf(m1 - mmax), e2 = expf(m2 - mmax);
        float rm1 = e1 / (e0 + e1 + e2);
        s_rm1[t] = rm1;
        float q = rm1 * (1.0f / 1024.0f);   // exact /2^10
        s_q[t] = q;
        s_fg[t] = sigmoidf(mx[256 + t]);
    }
    __syncthreads();
    if (t == 0) {
        float ret = 1.0f;
#pragma unroll
        for (int r = 0; r < RR; r++) ret *= (1.0f - s_fg[r] * s_q[r]);
        float u = 1e-6f * ret;              // usage (constant over n)
        s_u = u;
        float ag = sigmoidf(mx[260]);
        float wg = sigmoidf(mx[261]);
        s_c1 = wg * ag * (1.0f - u);
        s_c2 = wg * (1.0f - ag) * (1.0f / 1024.0f);
        float sh = 1.0f;                    // exact sequential cumprod prefix
#pragma unroll
        for (int i = 0; i < 16; i++) { s_pw[i] = sh; sh *= u; }
    }
    __syncthreads();

    // out[b, w*4+r] = 1e-6 * rm1[r]   (write-only -> evict-first)
    if (t < 128) {
        float4 ov = make_float4(1e-6f * s_rm1[0], 1e-6f * s_rm1[1],
                                1e-6f * s_rm1[2], 1e-6f * s_rm1[3]);
        __stcs(&((float4*)(out + OUT_OFF))[b * 128 + t], ov);
    }
    // ww (re-read by node 3 -> cached store) / prec / usage / rw (write-only)
    float c1 = s_c1, c2 = s_c2, u = s_u;
    float4 q4 = make_float4(s_q[0], s_q[1], s_q[2], s_q[3]);
#pragma unroll
    for (int n = t; n < NN; n += 256) {
        float shifted = (n < 16) ? s_pw[n] : 0.0f;
        float ww = fmaf(c1, shifted, c2);
        out[WWO_OFF + (size_t)b * NN + n] = ww;              // cached: node 3 re-reads
        __stcs(out + PREC_OFF + (size_t)b * NN + n, ww);
        __stcs(out + USAGE_OFF + (size_t)b * NN + n, u);
        __stcs(&((float4*)(out + RW_OFF))[b * NN + n], q4);
    }
}

// ---------------------------------------------------------------------------
// Node 3: PURE WRITE. memory fill (17MB) + link zero (134MB), all __stcs.
// grid 3072 x 256: bid<1024 memory (4 f4/thread), else link (16 f4/thread).
// ---------------------------------------------------------------------------
__global__ void __launch_bounds__(256)
k3_write(float* __restrict__ out) {
    int bid = blockIdx.x, t = threadIdx.x;
    if (bid < MEM_BLKS) {
        int base = bid * 1024 + t;
#pragma unroll
        for (int i = 0; i < 4; i++) {
            int v = base + i * 256;             // float4 index into memory
            int b = v >> 15;                     // 32768 f4 per batch
            int rem = v & 32767;
            int n  = rem >> 5;
            int w4 = rem & 31;
            float ww = __ldg(out + WWO_OFF + (size_t)b * NN + n);
            float4 e  = ((const float4*)g_er)[b * 32 + w4];
            float4 wv = ((const float4*)g_wv)[b * 32 + w4];
            float4 m;
            m.x = 1e-6f * (1.0f - ww * e.x) + ww * wv.x;
            m.y = 1e-6f * (1.0f - ww * e.y) + ww * wv.y;
            m.z = 1e-6f * (1.0f - ww * e.z) + ww * wv.z;
            m.w = 1e-6f * (1.0f - ww * e.w) + ww * wv.w;
            __stcs(&((float4*)(out + MEM_OFF))[v], m);
        }
    } else {
        float4 z = make_float4(0.f, 0.f, 0.f, 0.f);
        float4* p = (float4*)(out + LINK_OFF);
        size_t base = (size_t)(bid - MEM_BLKS) * 256 + t;
        size_t stride = (size_t)ZERO_BLKS * 256;
#pragma unroll
        for (int i = 0; i < 16; i++)            // exact cover, no bounds check
            __stcs(&p[base + (size_t)i * stride], z);
    }
}

extern "C" void kernel_launch(void* const* d_in, const int* in_sizes, int n_in,
                              void* d_out, int out_size) {
    const float* x  = (const float*)d_in[0];
    const float* Wm = (const float*)d_in[1];
    float* out = (float*)d_out;

    k1_mean<<<1024, 256>>>(x);
    k2_batch<<<BB, 256>>>(Wm, out);
    k3_write<<<N3_BLKS, 256>>>(out);
}